// round 14
// baseline (speedup 1.0000x reference)
#include <cuda_runtime.h>
#include <cuda_bf16.h>
#include <cstdint>
#include <cstddef>

// Problem constants
#define BB 128
#define NN 1024
#define LL 512
#define DD 64
#define MT 128                    // tokens per M tile
#define NMT (NN / MT)             // 8 M tiles
#define NTICKET (3 * BB * NMT)    // 3072 work items
#define TPB 128                   // 4 warps; warp owns 32 token rows
#define GRID 296                  // 148 SMs x 2 CTAs
#define RB 64                     // regions per B chunk
#define STRIDE 144                // padded smem row stride bytes -> LDSM conflict-free

// Scratch (no device allocations allowed -> __device__ globals)
__device__ __align__(16) __nv_bfloat16 g_thi[BB * NN * DD];
__device__ __align__(16) __nv_bfloat16 g_tlo[BB * NN * DD];
__device__ __align__(16) __nv_bfloat16 g_ihi[BB * LL * DD];
__device__ __align__(16) __nv_bfloat16 g_ilo[BB * LL * DD];
__device__ float         g_part[NTICKET];
__device__ float         g_ntokf[BB];
__device__ int           g_ntok[BB];
__device__ int           g_nreg[BB];
__device__ unsigned int  g_ticket;   // zero-init; reset by last block
__device__ unsigned int  g_done;

// ---------------------------------------------------------------------------
// PTX helpers (base sm_103 target: sm_80+ features only)
// ---------------------------------------------------------------------------
__device__ __forceinline__ uint32_t smem_to_u32(const void* p) {
    uint32_t a;
    asm("{ .reg .u64 t; cvta.to.shared.u64 t, %1; cvt.u32.u64 %0, t; }"
        : "=r"(a) : "l"(p));
    return a;
}

#define LDSM4(r, addr) \
    asm volatile("ldmatrix.sync.aligned.m8n8.x4.shared.b16 {%0,%1,%2,%3}, [%4];" \
        : "=r"((r)[0]), "=r"((r)[1]), "=r"((r)[2]), "=r"((r)[3]) : "r"(addr))

#define MMA16816(d, a, b) \
    asm volatile("mma.sync.aligned.m16n8k16.row.col.f32.bf16.bf16.f32 " \
        "{%0,%1,%2,%3}, {%4,%5,%6,%7}, {%8,%9}, {%0,%1,%2,%3};" \
        : "+f"((d)[0]), "+f"((d)[1]), "+f"((d)[2]), "+f"((d)[3]) \
        : "r"((a)[0]), "r"((a)[1]), "r"((a)[2]), "r"((a)[3]), \
          "r"((b)[0]), "r"((b)[1]))

#define CP_ASYNC16(dst_s, src_g) \
    asm volatile("cp.async.cg.shared.global [%0], [%1], 16;" :: "r"(dst_s), "l"(src_g))
#define CP_COMMIT() asm volatile("cp.async.commit_group;" ::: "memory")
#define CP_WAITG1() asm volatile("cp.async.wait_group 1;" ::: "memory")

// ldmatrix x4 address for A tile: 16x16 -> mats [r0-7,k0-7][r8-15,k0-7][r0-7,k8-15][r8-15,k8-15]
__device__ __forceinline__ uint32_t a_addr(uint32_t base, int row0, int kb, int lane) {
    int r = row0 + (lane & 7) + ((lane >> 3) & 1) * 8;
    return base + r * STRIDE + kb + ((lane >> 4) & 1) * 16;
}
// ldmatrix x4 address for TWO B n-tiles: mats [n0-7,k0-7][n0-7,k8-15][n8-15,k0-7][n8-15,k8-15]
__device__ __forceinline__ uint32_t b_addr4(uint32_t base, int nrow0, int kb, int lane) {
    int r = nrow0 + ((lane >> 4) & 1) * 8 + (lane & 7);
    return base + r * STRIDE + kb + ((lane >> 3) & 1) * 16;
}

// ---------------------------------------------------------------------------
// convert: fp32 -> (hi, lo) bf16 split; first BB blocks also count mask prefixes
// ---------------------------------------------------------------------------
__global__ void convert_kernel(const float* __restrict__ text,
                               const float* __restrict__ image,
                               const float* __restrict__ tmask,
                               const float* __restrict__ imask) {
    if (blockIdx.x < BB) {
        const int b = blockIdx.x;
        float sa = 0.f, sb = 0.f;
        for (int i = threadIdx.x; i < NN; i += blockDim.x) sa += tmask[b * NN + i];
        for (int i = threadIdx.x; i < LL; i += blockDim.x) sb += imask[b * LL + i];
        __shared__ float red[16];
        #pragma unroll
        for (int o = 16; o > 0; o >>= 1) {
            sa += __shfl_down_sync(0xffffffffu, sa, o);
            sb += __shfl_down_sync(0xffffffffu, sb, o);
        }
        int w = threadIdx.x >> 5, lane = threadIdx.x & 31;
        if (lane == 0) { red[2 * w] = sa; red[2 * w + 1] = sb; }
        __syncthreads();
        if (threadIdx.x == 0) {
            float ta = 0.f, tbv = 0.f;
            #pragma unroll
            for (int i = 0; i < 8; i++) { ta += red[2 * i]; tbv += red[2 * i + 1]; }
            g_ntokf[b] = ta;
            g_ntok[b] = (int)(ta + 0.5f);
            g_nreg[b] = (int)(tbv + 0.5f);
        }
    }

    const int NT4 = (BB * NN * DD) / 4;
    const int NI4 = (BB * LL * DD) / 4;
    int idx = blockIdx.x * blockDim.x + threadIdx.x;
    int stride = gridDim.x * blockDim.x;
    for (int i = idx; i < NT4 + NI4; i += stride) {
        const float4* src; __nv_bfloat16 *hi, *lo; int j;
        if (i < NT4) { src = (const float4*)text;  hi = g_thi; lo = g_tlo; j = i; }
        else         { src = (const float4*)image; hi = g_ihi; lo = g_ilo; j = i - NT4; }
        float4 v = src[j];
        __nv_bfloat16 h[4], l[4];
        h[0] = __float2bfloat16_rn(v.x); l[0] = __float2bfloat16_rn(v.x - __bfloat162float(h[0]));
        h[1] = __float2bfloat16_rn(v.y); l[1] = __float2bfloat16_rn(v.y - __bfloat162float(h[1]));
        h[2] = __float2bfloat16_rn(v.z); l[2] = __float2bfloat16_rn(v.z - __bfloat162float(h[2]));
        h[3] = __float2bfloat16_rn(v.w); l[3] = __float2bfloat16_rn(v.w - __bfloat162float(h[3]));
        *reinterpret_cast<uint2*>(hi + 4 * (size_t)j) = *reinterpret_cast<uint2*>(h);
        *reinterpret_cast<uint2*>(lo + 4 * (size_t)j) = *reinterpret_cast<uint2*>(l);
    }
}

// ---------------------------------------------------------------------------
// Dynamic SMEM layout:
//   [0..16)    s_tkt
//   [16..64)   rsm (reduction scratch)
//   [1024..)   A: 256 rows x 144 B (rows 0-127 = Ahi tokens, 128-255 = Alo)
//   then       B: 3 ring stages x 128 rows x 144 B (rows 0-63 = Bhi, 64-127 = Blo)
// ---------------------------------------------------------------------------
#define SM_TKT   0
#define SM_RSM   16
#define SM_A     1024
#define A_BYTES  (256 * STRIDE)          // 36864
#define SM_B0    (SM_A + A_BYTES)        // 37888
#define B_BYTES  (128 * STRIDE)          // 18432
#define SM_TOTAL (SM_B0 + 3 * B_BYTES)   // 93184 -> 2 CTAs/SM

// Full B chunk load: 64 hi rows + 64 lo rows (1024 x 16B) into a ring stage
__device__ __forceinline__ void load_b_full(uint32_t dstb, const char* ihi,
                                            const char* ilo, int row0, int t) {
    #pragma unroll
    for (int i = 0; i < 1024 / TPB; i++) {
        int idx = i * TPB + t;
        int r = idx >> 3, j = idx & 7;
        const char* src = (r < 64) ? ihi + (row0 + r) * 128 + j * 16
                                   : ilo + (row0 + r - 64) * 128 + j * 16;
        CP_ASYNC16(dstb + r * STRIDE + j * 16, src);
    }
}
// Partial B chunk load (lc rows of hi + lo)
__device__ __forceinline__ void load_b_part(uint32_t dstb, const char* ihi,
                                            const char* ilo, int row0, int lc, int t) {
    for (int i = t; i < lc * 16; i += TPB) {
        int half = (i >= lc * 8);
        int ii = i - half * lc * 8;
        int r = ii >> 3, j = ii & 7;
        const char* src = (half ? ilo : ihi) + (row0 + r) * 128 + j * 16;
        CP_ASYNC16(dstb + (half * 64 + r) * STRIDE + j * 16, src);
    }
}

// ---------------------------------------------------------------------------
__global__ __launch_bounds__(TPB) void main_kernel(
    const int* __restrict__ Iidx,
    const int* __restrict__ Sidx,
    float* __restrict__ out) {
    extern __shared__ char smem[];
    const uint32_t sbase = smem_to_u32(smem);
    float* rsm = (float*)(smem + SM_RSM);
    volatile unsigned* s_tkt = (volatile unsigned*)(smem + SM_TKT);
    const int t = threadIdx.x, w = t >> 5, lane = t & 31;

    unsigned prev_tk = 0xffffffffu;          // thread 0 only: pending result slot

    for (;;) {
        __syncthreads();                     // rsm written, all stages free
        if (t == 0) {
            if (prev_tk != 0xffffffffu)      // flush previous ticket's result
                g_part[prev_tk] = rsm[0] + rsm[1] + rsm[2] + rsm[3];
            unsigned tk;
            for (;;) {                       // skip zero-work tickets inline
                tk = atomicAdd(&g_ticket, 1u);
                if (tk >= NTICKET) break;
                int mtile = tk % NMT;
                int b = (tk / NMT) % BB;
                int s = tk / (BB * NMT);
                int tb = (s == 1) ? Sidx[b] : b;
                if (mtile * MT < g_ntok[tb]) break;
                g_part[tk] = 0.f;
            }
            *s_tkt = tk;
            prev_tk = (tk < NTICKET) ? tk : 0xffffffffu;
        }
        __syncthreads();
        const unsigned tk = *s_tkt;
        if (tk >= NTICKET) break;

        const int mtile = tk % NMT;
        const int b     = (tk / NMT) % BB;
        const int s     = tk / (BB * NMT);
        const int tb    = (s == 1) ? Sidx[b] : b;   // text batch index
        const int ib    = (s == 2) ? Iidx[b] : b;   // image batch index
        const int ntok  = g_ntok[tb];
        const int nreg  = g_nreg[ib];
        const int mbase = mtile * MT;

        // --- stage A (128 hi + 128 lo rows) + B chunk 0 -> group 1 ---
        {
            const char* thi = (const char*)(g_thi + ((size_t)tb * NN + mbase) * DD);
            const char* tlo = (const char*)(g_tlo + ((size_t)tb * NN + mbase) * DD);
            #pragma unroll
            for (int i = 0; i < 2048 / TPB; i++) {    // 256 rows x 8 chunks
                int idx = i * TPB + t;
                int r = idx >> 3, j = idx & 7;
                const char* src = (r < 128) ? thi + r * 128 + j * 16
                                            : tlo + (r - 128) * 128 + j * 16;
                CP_ASYNC16(sbase + SM_A + r * STRIDE + j * 16, src);
            }
        }
        const char* ihi = (const char*)(g_ihi + (size_t)ib * LL * DD);
        const char* ilo = (const char*)(g_ilo + (size_t)ib * LL * DD);
        const int nchunk = (nreg + RB - 1) / RB;      // >= 2 (nreg >= 128)

        load_b_full(sbase + SM_B0, ihi, ilo, 0, t);   // chunk 0 always full
        CP_COMMIT();                                  // G1 = A + B0
        if (nchunk >= 2) {                            // chunk 1 (maybe partial)
            int lc1 = nreg - RB; if (lc1 > RB) lc1 = RB;
            if (lc1 == RB) load_b_full(sbase + SM_B0 + B_BYTES, ihi, ilo, RB, t);
            else           load_b_part(sbase + SM_B0 + B_BYTES, ihi, ilo, RB, lc1, t);
        }
        CP_COMMIT();                                  // G2 = B1

        float mx0 = __int_as_float(0xff800000), mx1 = mx0, mx2 = mx0, mx3 = mx0;
        const uint32_t Abase = sbase + SM_A;

        // A fragments cached in registers across all chunks (loop-invariant)
        uint32_t ah[2][4][4], al[2][4][4];   // [mtile][kstep][frag]

        for (int c = 0; c < nchunk; c++) {
            CP_WAITG1();                     // B(c) resident (A too, via G1)
            __syncthreads();                 // everyone done with chunk c-1

            // prefetch chunk c+2 into stage (c+2)%3 (prior occupant = c-1, free)
            if (c + 2 < nchunk) {
                int cb2 = (c + 2) * RB;
                int lc2 = nreg - cb2; if (lc2 > RB) lc2 = RB;
                uint32_t dstb = sbase + SM_B0 + ((c + 2) % 3) * B_BYTES;
                if (lc2 == RB) load_b_full(dstb, ihi, ilo, cb2, t);
                else           load_b_part(dstb, ihi, ilo, cb2, lc2, t);
            }
            CP_COMMIT();                     // exactly one group per iteration

            if (c == 0) {                    // one-time A fragment load
                #pragma unroll
                for (int k = 0; k < 4; k++) {
                    LDSM4(ah[0][k], a_addr(Abase, 32 * w,            32 * k, lane));
                    LDSM4(ah[1][k], a_addr(Abase, 32 * w + 16,       32 * k, lane));
                    LDSM4(al[0][k], a_addr(Abase, 128 + 32 * w,      32 * k, lane));
                    LDSM4(al[1][k], a_addr(Abase, 128 + 32 * w + 16, 32 * k, lane));
                }
            }

            const uint32_t Bbase = sbase + SM_B0 + (c % 3) * B_BYTES;
            const int cb = c * RB;
            const int nvalid = nreg - cb;

            if (nvalid >= RB) {
                // ---- full chunk: fully unrolled ----
                float acc[8][2][4] = {};
                #pragma unroll
                for (int k = 0; k < 4; k++) {
                    const int kb = 32 * k;
                    uint32_t bh[8][2], bl[8][2];
                    #pragma unroll
                    for (int np = 0; np < 4; np++) {
                        uint32_t r4[4];
                        LDSM4(r4, b_addr4(Bbase, 16 * np, kb, lane));
                        bh[2 * np][0] = r4[0]; bh[2 * np][1] = r4[1];
                        bh[2 * np + 1][0] = r4[2]; bh[2 * np + 1][1] = r4[3];
                        LDSM4(r4, b_addr4(Bbase, 64 + 16 * np, kb, lane));
                        bl[2 * np][0] = r4[0]; bl[2 * np][1] = r4[1];
                        bl[2 * np + 1][0] = r4[2]; bl[2 * np + 1][1] = r4[3];
                    }
                    #pragma unroll
                    for (int nt = 0; nt < 8; nt++) {
                        MMA16816(acc[nt][0], ah[0][k], bh[nt]);
                        MMA16816(acc[nt][1], ah[1][k], bh[nt]);
                        MMA16816(acc[nt][0], ah[0][k], bl[nt]);
                        MMA16816(acc[nt][1], ah[1][k], bl[nt]);
                        MMA16816(acc[nt][0], al[0][k], bh[nt]);
                        MMA16816(acc[nt][1], al[1][k], bh[nt]);
                    }
                }
                #pragma unroll
                for (int nt = 0; nt < 8; nt++) {
                    mx0 = fmaxf(mx0, fmaxf(acc[nt][0][0], acc[nt][0][1]));
                    mx1 = fmaxf(mx1, fmaxf(acc[nt][0][2], acc[nt][0][3]));
                    mx2 = fmaxf(mx2, fmaxf(acc[nt][1][0], acc[nt][1][1]));
                    mx3 = fmaxf(mx3, fmaxf(acc[nt][1][2], acc[nt][1][3]));
                }
            } else {
                // ---- tail chunk: only ceil(nvalid/8) n-tiles ----
                const int ntmax = (nvalid + 7) >> 3;      // 1..8
                const int npmax = (ntmax + 1) >> 1;
                float acc[8][2][4] = {};
                for (int k = 0; k < 4; k++) {
                    const int kb = 32 * k;
                    uint32_t bh[8][2], bl[8][2];
                    for (int np = 0; np < npmax; np++) {
                        uint32_t r4[4];
                        LDSM4(r4, b_addr4(Bbase, 16 * np, kb, lane));
                        bh[2 * np][0] = r4[0]; bh[2 * np][1] = r4[1];
                        bh[2 * np + 1][0] = r4[2]; bh[2 * np + 1][1] = r4[3];
                        LDSM4(r4, b_addr4(Bbase, 64 + 16 * np, kb, lane));
                        bl[2 * np][0] = r4[0]; bl[2 * np][1] = r4[1];
                        bl[2 * np + 1][0] = r4[2]; bl[2 * np + 1][1] = r4[3];
                    }
                    for (int nt = 0; nt < ntmax; nt++) {
                        MMA16816(acc[nt][0], ah[0][k], bh[nt]);
                        MMA16816(acc[nt][1], ah[1][k], bh[nt]);
                        MMA16816(acc[nt][0], ah[0][k], bl[nt]);
                        MMA16816(acc[nt][1], ah[1][k], bl[nt]);
                        MMA16816(acc[nt][0], al[0][k], bh[nt]);
                        MMA16816(acc[nt][1], al[1][k], bh[nt]);
                    }
                }
                for (int nt = 0; nt < ntmax; nt++) {
                    const int c0 = cb + 8 * nt + 2 * (lane & 3);
                    if (c0 < nreg) {
                        mx0 = fmaxf(mx0, acc[nt][0][0]);
                        mx1 = fmaxf(mx1, acc[nt][0][2]);
                        mx2 = fmaxf(mx2, acc[nt][1][0]);
                        mx3 = fmaxf(mx3, acc[nt][1][2]);
                    }
                    if (c0 + 1 < nreg) {
                        mx0 = fmaxf(mx0, acc[nt][0][1]);
                        mx1 = fmaxf(mx1, acc[nt][0][3]);
                        mx2 = fmaxf(mx2, acc[nt][1][1]);
                        mx3 = fmaxf(mx3, acc[nt][1][3]);
                    }
                }
            }
            // no trailing barrier: next iter's barrier protects the ring
        }

        // --- quad max-reduce (cols live across the 4 lanes of each quad) ---
        mx0 = fmaxf(mx0, __shfl_xor_sync(0xffffffffu, mx0, 1));
        mx0 = fmaxf(mx0, __shfl_xor_sync(0xffffffffu, mx0, 2));
        mx1 = fmaxf(mx1, __shfl_xor_sync(0xffffffffu, mx1, 1));
        mx1 = fmaxf(mx1, __shfl_xor_sync(0xffffffffu, mx1, 2));
        mx2 = fmaxf(mx2, __shfl_xor_sync(0xffffffffu, mx2, 1));
        mx2 = fmaxf(mx2, __shfl_xor_sync(0xffffffffu, mx2, 2));
        mx3 = fmaxf(mx3, __shfl_xor_sync(0xffffffffu, mx3, 1));
        mx3 = fmaxf(mx3, __shfl_xor_sync(0xffffffffu, mx3, 2));

        // token-sum: rows mbase + 32w + lane/4 + {0,8,16,24}; weight = valid
        float v = 0.f;
        if ((lane & 3) == 0) {
            const int r0 = mbase + 32 * w + (lane >> 2);
            if (r0      < ntok) v += mx0;
            if (r0 + 8  < ntok) v += mx1;
            if (r0 + 16 < ntok) v += mx2;
            if (r0 + 24 < ntok) v += mx3;
        }
        #pragma unroll
        for (int o = 16; o > 0; o >>= 1) v += __shfl_down_sync(0xffffffffu, v, o);
        if (lane == 0) rsm[w] = v;
        // result flushed by thread 0 after the next fetch barrier
    }

    // ---- completion: last block computes the loss and resets counters ----
    __threadfence();
    __shared__ unsigned int s_prev;
    if (t == 0) s_prev = atomicAdd(&g_done, 1u);
    __syncthreads();
    if (s_prev != GRID - 1) return;
    __threadfence();

    const int bb = t;                            // 128 threads == BB
    float anchor = 0.f, simp = 0.f, iimp = 0.f;
    #pragma unroll
    for (int m = 0; m < NMT; m++) {
        anchor += g_part[(0 * BB + bb) * NMT + m];
        simp   += g_part[(1 * BB + bb) * NMT + m];
        iimp   += g_part[(2 * BB + bb) * NMT + m];
    }
    const float nb = g_ntokf[bb];
    anchor /= nb;
    iimp   /= nb;
    simp   /= g_ntokf[Sidx[bb]];
    float per = fmaxf(1.f + iimp - anchor, 0.f) + fmaxf(1.f + simp - anchor, 0.f);

    #pragma unroll
    for (int o = 16; o > 0; o >>= 1) per += __shfl_down_sync(0xffffffffu, per, o);
    if (lane == 0) rsm[w] = per;
    __syncthreads();
    if (t == 0) {
        out[0] = (rsm[0] + rsm[1] + rsm[2] + rsm[3]) / (float)BB;
        g_ticket = 0u;                           // reset for next replay
        g_done   = 0u;
    }
}

// ---------------------------------------------------------------------------
extern "C" void kernel_launch(void* const* d_in, const int* in_sizes, int n_in,
                              void* d_out, int out_size) {
    const float* text  = (const float*)d_in[0];   // (B, N, D) f32
    const float* image = (const float*)d_in[1];   // (B, L, D) f32
    const float* tmask = (const float*)d_in[2];   // (B, N) f32
    const float* imask = (const float*)d_in[3];   // (B, L) f32
    const int*   Iidx  = (const int*)d_in[4];     // (B,) i32
    const int*   Sidx  = (const int*)d_in[5];     // (B,) i32
    (void)in_sizes; (void)n_in; (void)out_size;

    static int configured = 0;
    if (!configured) {
        cudaFuncSetAttribute(main_kernel,
                             cudaFuncAttributeMaxDynamicSharedMemorySize, SM_TOTAL);
        configured = 1;
    }

    convert_kernel<<<2048, 256>>>(text, image, tmask, imask);
    main_kernel<<<GRID, TPB, SM_TOTAL>>>(Iidx, Sidx, (float*)d_out);
}

// round 15
// speedup vs baseline: 1.5046x; 1.5046x over previous
#include <cuda_runtime.h>
#include <cuda_bf16.h>
#include <cstdint>
#include <cstddef>

// Problem constants
#define BB 128
#define NN 1024
#define LL 512
#define DD 64
#define MT 128                    // tokens per M tile
#define NMT (NN / MT)             // 8 M tiles
#define NTICKET (3 * BB * NMT)    // 3072 work items
#define TPB 128                   // 4 warps; warp owns 32 token rows
#define GRID 296                  // 148 SMs x 2 CTAs
#define RB 64                     // regions per B chunk
#define STRIDE 144                // padded smem row stride bytes -> LDSM conflict-free

// Scratch (no device allocations allowed -> __device__ globals)
__device__ __align__(16) __nv_bfloat16 g_thi[BB * NN * DD];
__device__ __align__(16) __nv_bfloat16 g_tlo[BB * NN * DD];
__device__ __align__(16) __nv_bfloat16 g_ihi[BB * LL * DD];
__device__ __align__(16) __nv_bfloat16 g_ilo[BB * LL * DD];
__device__ float         g_part[NTICKET];
__device__ float         g_ntokf[BB];
__device__ int           g_ntok[BB];
__device__ int           g_nreg[BB];
__device__ unsigned int  g_ticket;   // zero-init; reset by last block
__device__ unsigned int  g_done;

// ---------------------------------------------------------------------------
// PTX helpers (base sm_103 target: sm_80+ features only)
// ---------------------------------------------------------------------------
__device__ __forceinline__ uint32_t smem_to_u32(const void* p) {
    uint32_t a;
    asm("{ .reg .u64 t; cvta.to.shared.u64 t, %1; cvt.u32.u64 %0, t; }"
        : "=r"(a) : "l"(p));
    return a;
}

#define LDSM4(r, addr) \
    asm volatile("ldmatrix.sync.aligned.m8n8.x4.shared.b16 {%0,%1,%2,%3}, [%4];" \
        : "=r"((r)[0]), "=r"((r)[1]), "=r"((r)[2]), "=r"((r)[3]) : "r"(addr))

#define MMA16816(d, a, b) \
    asm volatile("mma.sync.aligned.m16n8k16.row.col.f32.bf16.bf16.f32 " \
        "{%0,%1,%2,%3}, {%4,%5,%6,%7}, {%8,%9}, {%0,%1,%2,%3};" \
        : "+f"((d)[0]), "+f"((d)[1]), "+f"((d)[2]), "+f"((d)[3]) \
        : "r"((a)[0]), "r"((a)[1]), "r"((a)[2]), "r"((a)[3]), \
          "r"((b)[0]), "r"((b)[1]))

#define CP_ASYNC16(dst_s, src_g) \
    asm volatile("cp.async.cg.shared.global [%0], [%1], 16;" :: "r"(dst_s), "l"(src_g))
#define CP_COMMIT() asm volatile("cp.async.commit_group;" ::: "memory")
#define CP_WAIT1()  asm volatile("cp.async.wait_group 1;" ::: "memory")

// ldmatrix x4 address for A tile: 16x16 -> mats [r0-7,k0-7][r8-15,k0-7][r0-7,k8-15][r8-15,k8-15]
__device__ __forceinline__ uint32_t a_addr(uint32_t base, int row0, int kb, int lane) {
    int r = row0 + (lane & 7) + ((lane >> 3) & 1) * 8;
    return base + r * STRIDE + kb + ((lane >> 4) & 1) * 16;
}
// ldmatrix x4 address for TWO B n-tiles: mats [n0-7,k0-7][n0-7,k8-15][n8-15,k0-7][n8-15,k8-15]
__device__ __forceinline__ uint32_t b_addr4(uint32_t base, int nrow0, int kb, int lane) {
    int r = nrow0 + ((lane >> 4) & 1) * 8 + (lane & 7);
    return base + r * STRIDE + kb + ((lane >> 3) & 1) * 16;
}

// Fully-unrolled chunk compute over the first NT_ n-tiles (NT_ even, static
// register indexing everywhere -> no local-memory spill).
template <int NT_>
__device__ __forceinline__ void compute_chunk(
    float (&acc)[8][2][4], uint32_t Bbase, int lane,
    const uint32_t (&ah)[2][4][4], const uint32_t (&al)[2][4][4]) {
    #pragma unroll
    for (int k = 0; k < 4; k++) {
        const int kb = 32 * k;
        uint32_t bh[8][2], bl[8][2];
        #pragma unroll
        for (int np = 0; np < NT_ / 2; np++) {       // x4 loads 2 n-tiles each
            uint32_t r4[4];
            LDSM4(r4, b_addr4(Bbase, 16 * np, kb, lane));
            bh[2 * np][0] = r4[0]; bh[2 * np][1] = r4[1];
            bh[2 * np + 1][0] = r4[2]; bh[2 * np + 1][1] = r4[3];
            LDSM4(r4, b_addr4(Bbase, 64 + 16 * np, kb, lane));
            bl[2 * np][0] = r4[0]; bl[2 * np][1] = r4[1];
            bl[2 * np + 1][0] = r4[2]; bl[2 * np + 1][1] = r4[3];
        }
        // D = Ahi Bhi + Ahi Blo + Alo Bhi (fp32 accum)
        #pragma unroll
        for (int nt = 0; nt < NT_; nt++) {
            MMA16816(acc[nt][0], ah[0][k], bh[nt]);
            MMA16816(acc[nt][1], ah[1][k], bh[nt]);
            MMA16816(acc[nt][0], ah[0][k], bl[nt]);
            MMA16816(acc[nt][1], ah[1][k], bl[nt]);
            MMA16816(acc[nt][0], al[0][k], bh[nt]);
            MMA16816(acc[nt][1], al[1][k], bh[nt]);
        }
    }
}

// ---------------------------------------------------------------------------
// convert: fp32 -> (hi, lo) bf16 split; first BB blocks also count mask prefixes
// ---------------------------------------------------------------------------
__global__ void convert_kernel(const float* __restrict__ text,
                               const float* __restrict__ image,
                               const float* __restrict__ tmask,
                               const float* __restrict__ imask) {
    if (blockIdx.x < BB) {
        const int b = blockIdx.x;
        float sa = 0.f, sb = 0.f;
        for (int i = threadIdx.x; i < NN; i += blockDim.x) sa += tmask[b * NN + i];
        for (int i = threadIdx.x; i < LL; i += blockDim.x) sb += imask[b * LL + i];
        __shared__ float red[16];
        #pragma unroll
        for (int o = 16; o > 0; o >>= 1) {
            sa += __shfl_down_sync(0xffffffffu, sa, o);
            sb += __shfl_down_sync(0xffffffffu, sb, o);
        }
        int w = threadIdx.x >> 5, lane = threadIdx.x & 31;
        if (lane == 0) { red[2 * w] = sa; red[2 * w + 1] = sb; }
        __syncthreads();
        if (threadIdx.x == 0) {
            float ta = 0.f, tbv = 0.f;
            #pragma unroll
            for (int i = 0; i < 8; i++) { ta += red[2 * i]; tbv += red[2 * i + 1]; }
            g_ntokf[b] = ta;
            g_ntok[b] = (int)(ta + 0.5f);
            g_nreg[b] = (int)(tbv + 0.5f);
        }
    }

    const int NT4 = (BB * NN * DD) / 4;
    const int NI4 = (BB * LL * DD) / 4;
    int idx = blockIdx.x * blockDim.x + threadIdx.x;
    int stride = gridDim.x * blockDim.x;
    for (int i = idx; i < NT4 + NI4; i += stride) {
        const float4* src; __nv_bfloat16 *hi, *lo; int j;
        if (i < NT4) { src = (const float4*)text;  hi = g_thi; lo = g_tlo; j = i; }
        else         { src = (const float4*)image; hi = g_ihi; lo = g_ilo; j = i - NT4; }
        float4 v = src[j];
        __nv_bfloat16 h[4], l[4];
        h[0] = __float2bfloat16_rn(v.x); l[0] = __float2bfloat16_rn(v.x - __bfloat162float(h[0]));
        h[1] = __float2bfloat16_rn(v.y); l[1] = __float2bfloat16_rn(v.y - __bfloat162float(h[1]));
        h[2] = __float2bfloat16_rn(v.z); l[2] = __float2bfloat16_rn(v.z - __bfloat162float(h[2]));
        h[3] = __float2bfloat16_rn(v.w); l[3] = __float2bfloat16_rn(v.w - __bfloat162float(h[3]));
        *reinterpret_cast<uint2*>(hi + 4 * (size_t)j) = *reinterpret_cast<uint2*>(h);
        *reinterpret_cast<uint2*>(lo + 4 * (size_t)j) = *reinterpret_cast<uint2*>(l);
    }
}

// ---------------------------------------------------------------------------
// Dynamic SMEM layout:
//   [0..16)    s_tkt
//   [16..64)   rsm (reduction scratch)
//   [1024..)   A: 256 rows x 144 B (rows 0-127 = Ahi tokens, 128-255 = Alo)
//   then       B: 2 buffers x 128 rows x 144 B (rows 0-63 = Bhi, 64-127 = Blo)
// ---------------------------------------------------------------------------
#define SM_TKT   0
#define SM_RSM   16
#define SM_A     1024
#define A_BYTES  (256 * STRIDE)          // 36864
#define SM_B0    (SM_A + A_BYTES)        // 37888
#define B_BYTES  (128 * STRIDE)          // 18432
#define SM_TOTAL (SM_B0 + 2 * B_BYTES)   // 74752

// ---------------------------------------------------------------------------
__global__ __launch_bounds__(TPB) void main_kernel(
    const int* __restrict__ Iidx,
    const int* __restrict__ Sidx,
    float* __restrict__ out) {
    extern __shared__ char smem[];
    const uint32_t sbase = smem_to_u32(smem);
    float* rsm = (float*)(smem + SM_RSM);
    volatile unsigned* s_tkt = (volatile unsigned*)(smem + SM_TKT);
    const int t = threadIdx.x, w = t >> 5, lane = t & 31;

    for (;;) {
        __syncthreads();                     // protect s_tkt / rsm / smem reuse
        if (t == 0) {
            unsigned tk;
            for (;;) {                       // skip zero-work tickets inline
                tk = atomicAdd(&g_ticket, 1u);
                if (tk >= NTICKET) break;
                int mtile = tk % NMT;
                int bz = (tk / NMT) % BB;
                int sz = tk / (BB * NMT);
                int tbz = (sz == 1) ? Sidx[bz] : bz;
                if (mtile * MT < g_ntok[tbz]) break;
                g_part[tk] = 0.f;
            }
            *s_tkt = tk;
        }
        __syncthreads();
        const unsigned tk = *s_tkt;
        if (tk >= NTICKET) break;

        const int mtile = tk % NMT;
        const int b     = (tk / NMT) % BB;
        const int s     = tk / (BB * NMT);
        const int tb    = (s == 1) ? Sidx[b] : b;   // text batch index
        const int ib    = (s == 2) ? Iidx[b] : b;   // image batch index
        const int ntok  = g_ntok[tb];
        const int nreg  = g_nreg[ib];
        const int mbase = mtile * MT;                // guaranteed < ntok

        // --- stage A (128 rows hi + 128 rows lo) via cp.async ---
        {
            const char* thi = (const char*)(g_thi + ((size_t)tb * NN + mbase) * DD);
            const char* tlo = (const char*)(g_tlo + ((size_t)tb * NN + mbase) * DD);
            #pragma unroll
            for (int i = 0; i < 2048 / TPB; i++) {    // 256 rows x 8 chunks
                int idx = i * TPB + t;
                int r = idx >> 3, j = idx & 7;
                const char* src = (r < 128) ? thi + r * 128 + j * 16
                                            : tlo + (r - 128) * 128 + j * 16;
                CP_ASYNC16(sbase + SM_A + r * STRIDE + j * 16, src);
            }
        }
        const char* ihi = (const char*)(g_ihi + (size_t)ib * LL * DD);
        const char* ilo = (const char*)(g_ilo + (size_t)ib * LL * DD);
        const int nchunk = (nreg + RB - 1) / RB;      // >= 2 (nreg >= 128)

        // stage B chunk 0 (hi rows 0-63, lo rows 64-127); chunk 0 always full
        {
            #pragma unroll
            for (int i = 0; i < 1024 / TPB; i++) {    // 128 rows x 8 chunks
                int idx = i * TPB + t;
                int r = idx >> 3, j = idx & 7;
                const char* src = (r < 64) ? ihi + r * 128 + j * 16
                                           : ilo + (r - 64) * 128 + j * 16;
                CP_ASYNC16(sbase + SM_B0 + r * STRIDE + j * 16, src);
            }
        }
        CP_COMMIT();

        float mx0 = __int_as_float(0xff800000), mx1 = mx0, mx2 = mx0, mx3 = mx0;
        const uint32_t Abase = sbase + SM_A;

        // A fragments cached in registers across all chunks (loop-invariant)
        uint32_t ah[2][4][4], al[2][4][4];   // [mtile][kstep][frag]

        for (int c = 0; c < nchunk; c++) {
            if (c + 1 < nchunk) {                // prefetch next chunk
                int cb2 = (c + 1) * RB;
                int lc2 = nreg - cb2; if (lc2 > RB) lc2 = RB;
                uint32_t dstb = sbase + SM_B0 + ((c + 1) & 1) * B_BYTES;
                for (int i = t; i < lc2 * 16; i += TPB) {
                    int half = (i >= lc2 * 8);
                    int ii = i - half * lc2 * 8;
                    int r = ii >> 3, j = ii & 7;
                    const char* src = (half ? ilo : ihi) + (cb2 + r) * 128 + j * 16;
                    CP_ASYNC16(dstb + (half * 64 + r) * STRIDE + j * 16, src);
                }
            }
            CP_COMMIT();
            CP_WAIT1();                          // chunk c (and A on c==0) resident
            __syncthreads();

            if (c == 0) {                        // one-time A fragment load
                #pragma unroll
                for (int k = 0; k < 4; k++) {
                    LDSM4(ah[0][k], a_addr(Abase, 32 * w,            32 * k, lane));
                    LDSM4(ah[1][k], a_addr(Abase, 32 * w + 16,       32 * k, lane));
                    LDSM4(al[0][k], a_addr(Abase, 128 + 32 * w,      32 * k, lane));
                    LDSM4(al[1][k], a_addr(Abase, 128 + 32 * w + 16, 32 * k, lane));
                }
            }

            const uint32_t Bbase = sbase + SM_B0 + (c & 1) * B_BYTES;
            const int cb = c * RB;
            const int nvalid = nreg - cb;

            float acc[8][2][4] = {};             // 8 n-tiles x 2 m-tiles x 4

            if (nvalid >= RB) {
                compute_chunk<8>(acc, Bbase, lane, ah, al);
                #pragma unroll
                for (int nt = 0; nt < 8; nt++) {
                    mx0 = fmaxf(mx0, fmaxf(acc[nt][0][0], acc[nt][0][1]));
                    mx1 = fmaxf(mx1, fmaxf(acc[nt][0][2], acc[nt][0][3]));
                    mx2 = fmaxf(mx2, fmaxf(acc[nt][1][0], acc[nt][1][1]));
                    mx3 = fmaxf(mx3, fmaxf(acc[nt][1][2], acc[nt][1][3]));
                }
            } else {
                // ---- tail chunk: dispatch to static instance (no spills) ----
                const int pairs = (nvalid + 15) >> 4;     // 1..4
                switch (pairs) {
                    case 1:  compute_chunk<2>(acc, Bbase, lane, ah, al); break;
                    case 2:  compute_chunk<4>(acc, Bbase, lane, ah, al); break;
                    case 3:  compute_chunk<6>(acc, Bbase, lane, ah, al); break;
                    default: compute_chunk<8>(acc, Bbase, lane, ah, al); break;
                }
                #pragma unroll
                for (int nt = 0; nt < 8; nt++) {          // guarded masked fold
                    const int c0 = cb + 8 * nt + 2 * (lane & 3);
                    if (c0 < nreg) {
                        mx0 = fmaxf(mx0, acc[nt][0][0]);
                        mx1 = fmaxf(mx1, acc[nt][0][2]);
                        mx2 = fmaxf(mx2, acc[nt][1][0]);
                        mx3 = fmaxf(mx3, acc[nt][1][2]);
                    }
                    if (c0 + 1 < nreg) {
                        mx0 = fmaxf(mx0, acc[nt][0][1]);
                        mx1 = fmaxf(mx1, acc[nt][0][3]);
                        mx2 = fmaxf(mx2, acc[nt][1][1]);
                        mx3 = fmaxf(mx3, acc[nt][1][3]);
                    }
                }
            }
            __syncthreads();                     // chunk c free before c+2 load
        }

        // --- quad max-reduce (cols live across the 4 lanes of each quad) ---
        mx0 = fmaxf(mx0, __shfl_xor_sync(0xffffffffu, mx0, 1));
        mx0 = fmaxf(mx0, __shfl_xor_sync(0xffffffffu, mx0, 2));
        mx1 = fmaxf(mx1, __shfl_xor_sync(0xffffffffu, mx1, 1));
        mx1 = fmaxf(mx1, __shfl_xor_sync(0xffffffffu, mx1, 2));
        mx2 = fmaxf(mx2, __shfl_xor_sync(0xffffffffu, mx2, 1));
        mx2 = fmaxf(mx2, __shfl_xor_sync(0xffffffffu, mx2, 2));
        mx3 = fmaxf(mx3, __shfl_xor_sync(0xffffffffu, mx3, 1));
        mx3 = fmaxf(mx3, __shfl_xor_sync(0xffffffffu, mx3, 2));

        // token-sum: rows mbase + 32w + lane/4 + {0,8,16,24}; weight = valid
        float v = 0.f;
        if ((lane & 3) == 0) {
            const int r0 = mbase + 32 * w + (lane >> 2);
            if (r0      < ntok) v += mx0;
            if (r0 + 8  < ntok) v += mx1;
            if (r0 + 16 < ntok) v += mx2;
            if (r0 + 24 < ntok) v += mx3;
        }
        #pragma unroll
        for (int o = 16; o > 0; o >>= 1) v += __shfl_down_sync(0xffffffffu, v, o);
        if (lane == 0) rsm[w] = v;
        __syncthreads();
        if (t == 0) g_part[tk] = rsm[0] + rsm[1] + rsm[2] + rsm[3];
    }

    // ---- completion: last block computes the loss and resets counters ----
    __threadfence();
    __shared__ unsigned int s_prev;
    if (t == 0) s_prev = atomicAdd(&g_done, 1u);
    __syncthreads();
    if (s_prev != GRID - 1) return;
    __threadfence();

    const int bb = t;                            // 128 threads == BB
    float anchor = 0.f, simp = 0.f, iimp = 0.f;
    #pragma unroll
    for (int m = 0; m < NMT; m++) {
        anchor += g_part[(0 * BB + bb) * NMT + m];
        simp   += g_part[(1 * BB + bb) * NMT + m];
        iimp   += g_part[(2 * BB + bb) * NMT + m];
    }
    const float nb = g_ntokf[bb];
    anchor /= nb;
    iimp   /= nb;
    simp   /= g_ntokf[Sidx[bb]];
    float per = fmaxf(1.f + iimp - anchor, 0.f) + fmaxf(1.f + simp - anchor, 0.f);

    #pragma unroll
    for (int o = 16; o > 0; o >>= 1) per += __shfl_down_sync(0xffffffffu, per, o);
    if (lane == 0) rsm[w] = per;
    __syncthreads();
    if (t == 0) {
        out[0] = (rsm[0] + rsm[1] + rsm[2] + rsm[3]) / (float)BB;
        g_ticket = 0u;                           // reset for next replay
        g_done   = 0u;
    }
}

// ---------------------------------------------------------------------------
extern "C" void kernel_launch(void* const* d_in, const int* in_sizes, int n_in,
                              void* d_out, int out_size) {
    const float* text  = (const float*)d_in[0];   // (B, N, D) f32
    const float* image = (const float*)d_in[1];   // (B, L, D) f32
    const float* tmask = (const float*)d_in[2];   // (B, N) f32
    const float* imask = (const float*)d_in[3];   // (B, L) f32
    const int*   Iidx  = (const int*)d_in[4];     // (B,) i32
    const int*   Sidx  = (const int*)d_in[5];     // (B,) i32
    (void)in_sizes; (void)n_in; (void)out_size;

    static int configured = 0;
    if (!configured) {
        cudaFuncSetAttribute(main_kernel,
                             cudaFuncAttributeMaxDynamicSharedMemorySize, SM_TOTAL);
        configured = 1;
    }

    convert_kernel<<<2048, 256>>>(text, image, tmask, imask);
    main_kernel<<<GRID, TPB, SM_TOTAL>>>(Iidx, Sidx, (float*)d_out);
}

// round 16
// speedup vs baseline: 1.6009x; 1.0640x over previous
#include <cuda_runtime.h>
#include <cuda_bf16.h>
#include <cstdint>
#include <cstddef>

// Problem constants
#define BB 128
#define NN 1024
#define LL 512
#define DD 64
#define MT 128                    // tokens per M tile
#define NMT (NN / MT)             // 8 M tiles
#define NTICKET (3 * BB * NMT)    // 3072 work items
#define TPB 128                   // 4 warps; warp owns 32 token rows
#define GRID 296                  // 148 SMs x 2 CTAs
#define RB 64                     // regions per B chunk
#define STRIDE 144                // padded smem row stride bytes -> LDSM conflict-free

// Scratch (no device allocations allowed -> __device__ globals)
__device__ __align__(16) __nv_bfloat16 g_thi[BB * NN * DD];
__device__ __align__(16) __nv_bfloat16 g_tlo[BB * NN * DD];
__device__ __align__(16) __nv_bfloat16 g_ihi[BB * LL * DD];
__device__ __align__(16) __nv_bfloat16 g_ilo[BB * LL * DD];
__device__ float         g_part[NTICKET];
__device__ float         g_ntokf[BB];
__device__ int           g_ntok[BB];
__device__ int           g_nreg[BB];
__device__ unsigned int  g_ticket;   // zero-init; reset by last block
__device__ unsigned int  g_done;

// ---------------------------------------------------------------------------
// PTX helpers (base sm_103 target: sm_80+ features only)
// ---------------------------------------------------------------------------
__device__ __forceinline__ uint32_t smem_to_u32(const void* p) {
    uint32_t a;
    asm("{ .reg .u64 t; cvta.to.shared.u64 t, %1; cvt.u32.u64 %0, t; }"
        : "=r"(a) : "l"(p));
    return a;
}

#define LDSM4(r, addr) \
    asm volatile("ldmatrix.sync.aligned.m8n8.x4.shared.b16 {%0,%1,%2,%3}, [%4];" \
        : "=r"((r)[0]), "=r"((r)[1]), "=r"((r)[2]), "=r"((r)[3]) : "r"(addr))

#define MMA16816(d, a, b) \
    asm volatile("mma.sync.aligned.m16n8k16.row.col.f32.bf16.bf16.f32 " \
        "{%0,%1,%2,%3}, {%4,%5,%6,%7}, {%8,%9}, {%0,%1,%2,%3};" \
        : "+f"((d)[0]), "+f"((d)[1]), "+f"((d)[2]), "+f"((d)[3]) \
        : "r"((a)[0]), "r"((a)[1]), "r"((a)[2]), "r"((a)[3]), \
          "r"((b)[0]), "r"((b)[1]))

#define CP_ASYNC16(dst_s, src_g) \
    asm volatile("cp.async.cg.shared.global [%0], [%1], 16;" :: "r"(dst_s), "l"(src_g))
#define CP_COMMIT() asm volatile("cp.async.commit_group;" ::: "memory")
#define CP_WAITG1() asm volatile("cp.async.wait_group 1;" ::: "memory")

// ldmatrix x4 address for A tile: 16x16 -> mats [r0-7,k0-7][r8-15,k0-7][r0-7,k8-15][r8-15,k8-15]
__device__ __forceinline__ uint32_t a_addr(uint32_t base, int row0, int kb, int lane) {
    int r = row0 + (lane & 7) + ((lane >> 3) & 1) * 8;
    return base + r * STRIDE + kb + ((lane >> 4) & 1) * 16;
}
// ldmatrix x4 address for TWO B n-tiles: mats [n0-7,k0-7][n0-7,k8-15][n8-15,k0-7][n8-15,k8-15]
__device__ __forceinline__ uint32_t b_addr4(uint32_t base, int nrow0, int kb, int lane) {
    int r = nrow0 + ((lane >> 4) & 1) * 8 + (lane & 7);
    return base + r * STRIDE + kb + ((lane >> 3) & 1) * 16;
}

// Fully-unrolled chunk compute over the first NT_ n-tiles (NT_ even, static
// register indexing everywhere -> no local-memory spill).
template <int NT_>
__device__ __forceinline__ void compute_chunk(
    float (&acc)[8][2][4], uint32_t Bbase, int lane,
    const uint32_t (&ah)[2][4][4], const uint32_t (&al)[2][4][4]) {
    #pragma unroll
    for (int k = 0; k < 4; k++) {
        const int kb = 32 * k;
        uint32_t bh[8][2], bl[8][2];
        #pragma unroll
        for (int np = 0; np < NT_ / 2; np++) {       // x4 loads 2 n-tiles each
            uint32_t r4[4];
            LDSM4(r4, b_addr4(Bbase, 16 * np, kb, lane));
            bh[2 * np][0] = r4[0]; bh[2 * np][1] = r4[1];
            bh[2 * np + 1][0] = r4[2]; bh[2 * np + 1][1] = r4[3];
            LDSM4(r4, b_addr4(Bbase, 64 + 16 * np, kb, lane));
            bl[2 * np][0] = r4[0]; bl[2 * np][1] = r4[1];
            bl[2 * np + 1][0] = r4[2]; bl[2 * np + 1][1] = r4[3];
        }
        // D = Ahi Bhi + Ahi Blo + Alo Bhi (fp32 accum)
        #pragma unroll
        for (int nt = 0; nt < NT_; nt++) {
            MMA16816(acc[nt][0], ah[0][k], bh[nt]);
            MMA16816(acc[nt][1], ah[1][k], bh[nt]);
            MMA16816(acc[nt][0], ah[0][k], bl[nt]);
            MMA16816(acc[nt][1], ah[1][k], bl[nt]);
            MMA16816(acc[nt][0], al[0][k], bh[nt]);
            MMA16816(acc[nt][1], al[1][k], bh[nt]);
        }
    }
}

// ---------------------------------------------------------------------------
// convert: fp32 -> (hi, lo) bf16 split; first BB blocks also count mask prefixes
// ---------------------------------------------------------------------------
__global__ void convert_kernel(const float* __restrict__ text,
                               const float* __restrict__ image,
                               const float* __restrict__ tmask,
                               const float* __restrict__ imask) {
    if (blockIdx.x < BB) {
        const int b = blockIdx.x;
        float sa = 0.f, sb = 0.f;
        for (int i = threadIdx.x; i < NN; i += blockDim.x) sa += tmask[b * NN + i];
        for (int i = threadIdx.x; i < LL; i += blockDim.x) sb += imask[b * LL + i];
        __shared__ float red[16];
        #pragma unroll
        for (int o = 16; o > 0; o >>= 1) {
            sa += __shfl_down_sync(0xffffffffu, sa, o);
            sb += __shfl_down_sync(0xffffffffu, sb, o);
        }
        int w = threadIdx.x >> 5, lane = threadIdx.x & 31;
        if (lane == 0) { red[2 * w] = sa; red[2 * w + 1] = sb; }
        __syncthreads();
        if (threadIdx.x == 0) {
            float ta = 0.f, tbv = 0.f;
            #pragma unroll
            for (int i = 0; i < 8; i++) { ta += red[2 * i]; tbv += red[2 * i + 1]; }
            g_ntokf[b] = ta;
            g_ntok[b] = (int)(ta + 0.5f);
            g_nreg[b] = (int)(tbv + 0.5f);
        }
    }

    const int NT4 = (BB * NN * DD) / 4;
    const int NI4 = (BB * LL * DD) / 4;
    int idx = blockIdx.x * blockDim.x + threadIdx.x;
    int stride = gridDim.x * blockDim.x;
    for (int i = idx; i < NT4 + NI4; i += stride) {
        const float4* src; __nv_bfloat16 *hi, *lo; int j;
        if (i < NT4) { src = (const float4*)text;  hi = g_thi; lo = g_tlo; j = i; }
        else         { src = (const float4*)image; hi = g_ihi; lo = g_ilo; j = i - NT4; }
        float4 v = src[j];
        __nv_bfloat16 h[4], l[4];
        h[0] = __float2bfloat16_rn(v.x); l[0] = __float2bfloat16_rn(v.x - __bfloat162float(h[0]));
        h[1] = __float2bfloat16_rn(v.y); l[1] = __float2bfloat16_rn(v.y - __bfloat162float(h[1]));
        h[2] = __float2bfloat16_rn(v.z); l[2] = __float2bfloat16_rn(v.z - __bfloat162float(h[2]));
        h[3] = __float2bfloat16_rn(v.w); l[3] = __float2bfloat16_rn(v.w - __bfloat162float(h[3]));
        *reinterpret_cast<uint2*>(hi + 4 * (size_t)j) = *reinterpret_cast<uint2*>(h);
        *reinterpret_cast<uint2*>(lo + 4 * (size_t)j) = *reinterpret_cast<uint2*>(l);
    }
}

// ---------------------------------------------------------------------------
// Dynamic SMEM layout:
//   [0..16)    s_tkt
//   [16..64)   rsm (reduction scratch)
//   [1024..)   A: 256 rows x 144 B (rows 0-127 = Ahi tokens, 128-255 = Alo)
//   then       B: 3 ring stages x 128 rows x 144 B (rows 0-63 = Bhi, 64-127 = Blo)
// ---------------------------------------------------------------------------
#define SM_TKT   0
#define SM_RSM   16
#define SM_A     1024
#define A_BYTES  (256 * STRIDE)          // 36864
#define SM_B0    (SM_A + A_BYTES)        // 37888
#define B_BYTES  (128 * STRIDE)          // 18432
#define SM_TOTAL (SM_B0 + 3 * B_BYTES)   // 93184 -> 2 CTAs/SM

// Full B chunk load: 64 hi rows + 64 lo rows into a ring stage
__device__ __forceinline__ void load_b_full(uint32_t dstb, const char* ihi,
                                            const char* ilo, int row0, int t) {
    #pragma unroll
    for (int i = 0; i < 1024 / TPB; i++) {
        int idx = i * TPB + t;
        int r = idx >> 3, j = idx & 7;
        const char* src = (r < 64) ? ihi + (row0 + r) * 128 + j * 16
                                   : ilo + (row0 + r - 64) * 128 + j * 16;
        CP_ASYNC16(dstb + r * STRIDE + j * 16, src);
    }
}
// Partial B chunk load (lc rows of hi + lo)
__device__ __forceinline__ void load_b_part(uint32_t dstb, const char* ihi,
                                            const char* ilo, int row0, int lc, int t) {
    for (int i = t; i < lc * 16; i += TPB) {
        int half = (i >= lc * 8);
        int ii = i - half * lc * 8;
        int r = ii >> 3, j = ii & 7;
        const char* src = (half ? ilo : ihi) + (row0 + r) * 128 + j * 16;
        CP_ASYNC16(dstb + (half * 64 + r) * STRIDE + j * 16, src);
    }
}

// ---------------------------------------------------------------------------
__global__ __launch_bounds__(TPB) void main_kernel(
    const int* __restrict__ Iidx,
    const int* __restrict__ Sidx,
    float* __restrict__ out) {
    extern __shared__ char smem[];
    const uint32_t sbase = smem_to_u32(smem);
    float* rsm = (float*)(smem + SM_RSM);
    volatile unsigned* s_tkt = (volatile unsigned*)(smem + SM_TKT);
    const int t = threadIdx.x, w = t >> 5, lane = t & 31;

    for (;;) {
        __syncthreads();                     // protect s_tkt / rsm / smem reuse
        if (t == 0) {
            unsigned tk;
            for (;;) {                       // skip zero-work tickets inline
                tk = atomicAdd(&g_ticket, 1u);
                if (tk >= NTICKET) break;
                int mtile = tk % NMT;
                int bz = (tk / NMT) % BB;
                int sz = tk / (BB * NMT);
                int tbz = (sz == 1) ? Sidx[bz] : bz;
                if (mtile * MT < g_ntok[tbz]) break;
                g_part[tk] = 0.f;
            }
            *s_tkt = tk;
        }
        __syncthreads();
        const unsigned tk = *s_tkt;
        if (tk >= NTICKET) break;

        const int mtile = tk % NMT;
        const int b     = (tk / NMT) % BB;
        const int s     = tk / (BB * NMT);
        const int tb    = (s == 1) ? Sidx[b] : b;   // text batch index
        const int ib    = (s == 2) ? Iidx[b] : b;   // image batch index
        const int ntok  = g_ntok[tb];
        const int nreg  = g_nreg[ib];
        const int mbase = mtile * MT;                // guaranteed < ntok

        // --- stage A (128 rows hi + 128 rows lo) + B chunk 0 -> group 1 ---
        {
            const char* thi = (const char*)(g_thi + ((size_t)tb * NN + mbase) * DD);
            const char* tlo = (const char*)(g_tlo + ((size_t)tb * NN + mbase) * DD);
            #pragma unroll
            for (int i = 0; i < 2048 / TPB; i++) {    // 256 rows x 8 chunks
                int idx = i * TPB + t;
                int r = idx >> 3, j = idx & 7;
                const char* src = (r < 128) ? thi + r * 128 + j * 16
                                            : tlo + (r - 128) * 128 + j * 16;
                CP_ASYNC16(sbase + SM_A + r * STRIDE + j * 16, src);
            }
        }
        const char* ihi = (const char*)(g_ihi + (size_t)ib * LL * DD);
        const char* ilo = (const char*)(g_ilo + (size_t)ib * LL * DD);
        const int nchunk = (nreg + RB - 1) / RB;      // >= 2 (nreg >= 128)

        load_b_full(sbase + SM_B0, ihi, ilo, 0, t);   // chunk 0 always full
        CP_COMMIT();                                  // G1 = A + B0
        {                                             // chunk 1 (maybe partial)
            int lc1 = nreg - RB; if (lc1 > RB) lc1 = RB;
            if (lc1 == RB) load_b_full(sbase + SM_B0 + B_BYTES, ihi, ilo, RB, t);
            else           load_b_part(sbase + SM_B0 + B_BYTES, ihi, ilo, RB, lc1, t);
        }
        CP_COMMIT();                                  // G2 = B1

        float mx0 = __int_as_float(0xff800000), mx1 = mx0, mx2 = mx0, mx3 = mx0;
        const uint32_t Abase = sbase + SM_A;

        // A fragments cached in registers across all chunks (loop-invariant)
        uint32_t ah[2][4][4], al[2][4][4];   // [mtile][kstep][frag]

        for (int c = 0; c < nchunk; c++) {
            CP_WAITG1();                     // B(c) resident (A too, via G1)
            __syncthreads();                 // data visible; stage (c+2)%3 free
                                             // (its occupant c-1 drained by all)

            // prefetch chunk c+2 into stage (c+2)%3
            if (c + 2 < nchunk) {
                int cb2 = (c + 2) * RB;
                int lc2 = nreg - cb2; if (lc2 > RB) lc2 = RB;
                uint32_t dstb = sbase + SM_B0 + ((c + 2) % 3) * B_BYTES;
                if (lc2 == RB) load_b_full(dstb, ihi, ilo, cb2, t);
                else           load_b_part(dstb, ihi, ilo, cb2, lc2, t);
            }
            CP_COMMIT();                     // exactly one group per iteration

            if (c == 0) {                    // one-time A fragment load
                #pragma unroll
                for (int k = 0; k < 4; k++) {
                    LDSM4(ah[0][k], a_addr(Abase, 32 * w,            32 * k, lane));
                    LDSM4(ah[1][k], a_addr(Abase, 32 * w + 16,       32 * k, lane));
                    LDSM4(al[0][k], a_addr(Abase, 128 + 32 * w,      32 * k, lane));
                    LDSM4(al[1][k], a_addr(Abase, 128 + 32 * w + 16, 32 * k, lane));
                }
            }

            const uint32_t Bbase = sbase + SM_B0 + (c % 3) * B_BYTES;
            const int cb = c * RB;
            const int nvalid = nreg - cb;

            float acc[8][2][4] = {};             // 8 n-tiles x 2 m-tiles x 4

            if (nvalid >= RB) {
                compute_chunk<8>(acc, Bbase, lane, ah, al);
                #pragma unroll
                for (int nt = 0; nt < 8; nt++) {
                    mx0 = fmaxf(mx0, fmaxf(acc[nt][0][0], acc[nt][0][1]));
                    mx1 = fmaxf(mx1, fmaxf(acc[nt][0][2], acc[nt][0][3]));
                    mx2 = fmaxf(mx2, fmaxf(acc[nt][1][0], acc[nt][1][1]));
                    mx3 = fmaxf(mx3, fmaxf(acc[nt][1][2], acc[nt][1][3]));
                }
            } else {
                // ---- tail chunk: dispatch to static instance (no spills) ----
                const int pairs = (nvalid + 15) >> 4;     // 1..4
                switch (pairs) {
                    case 1:  compute_chunk<2>(acc, Bbase, lane, ah, al); break;
                    case 2:  compute_chunk<4>(acc, Bbase, lane, ah, al); break;
                    case 3:  compute_chunk<6>(acc, Bbase, lane, ah, al); break;
                    default: compute_chunk<8>(acc, Bbase, lane, ah, al); break;
                }
                #pragma unroll
                for (int nt = 0; nt < 8; nt++) {          // guarded masked fold
                    const int c0 = cb + 8 * nt + 2 * (lane & 3);
                    if (c0 < nreg) {
                        mx0 = fmaxf(mx0, acc[nt][0][0]);
                        mx1 = fmaxf(mx1, acc[nt][0][2]);
                        mx2 = fmaxf(mx2, acc[nt][1][0]);
                        mx3 = fmaxf(mx3, acc[nt][1][2]);
                    }
                    if (c0 + 1 < nreg) {
                        mx0 = fmaxf(mx0, acc[nt][0][1]);
                        mx1 = fmaxf(mx1, acc[nt][0][3]);
                        mx2 = fmaxf(mx2, acc[nt][1][1]);
                        mx3 = fmaxf(mx3, acc[nt][1][3]);
                    }
                }
            }
            // no trailing barrier: next iteration's barrier protects the ring
        }

        // --- quad max-reduce (cols live across the 4 lanes of each quad) ---
        mx0 = fmaxf(mx0, __shfl_xor_sync(0xffffffffu, mx0, 1));
        mx0 = fmaxf(mx0, __shfl_xor_sync(0xffffffffu, mx0, 2));
        mx1 = fmaxf(mx1, __shfl_xor_sync(0xffffffffu, mx1, 1));
        mx1 = fmaxf(mx1, __shfl_xor_sync(0xffffffffu, mx1, 2));
        mx2 = fmaxf(mx2, __shfl_xor_sync(0xffffffffu, mx2, 1));
        mx2 = fmaxf(mx2, __shfl_xor_sync(0xffffffffu, mx2, 2));
        mx3 = fmaxf(mx3, __shfl_xor_sync(0xffffffffu, mx3, 1));
        mx3 = fmaxf(mx3, __shfl_xor_sync(0xffffffffu, mx3, 2));

        // token-sum: rows mbase + 32w + lane/4 + {0,8,16,24}; weight = valid
        float v = 0.f;
        if ((lane & 3) == 0) {
            const int r0 = mbase + 32 * w + (lane >> 2);
            if (r0      < ntok) v += mx0;
            if (r0 + 8  < ntok) v += mx1;
            if (r0 + 16 < ntok) v += mx2;
            if (r0 + 24 < ntok) v += mx3;
        }
        #pragma unroll
        for (int o = 16; o > 0; o >>= 1) v += __shfl_down_sync(0xffffffffu, v, o);
        if (lane == 0) rsm[w] = v;
        __syncthreads();
        if (t == 0) g_part[tk] = rsm[0] + rsm[1] + rsm[2] + rsm[3];
    }

    // ---- completion: last block computes the loss and resets counters ----
    __threadfence();
    __shared__ unsigned int s_prev;
    if (t == 0) s_prev = atomicAdd(&g_done, 1u);
    __syncthreads();
    if (s_prev != GRID - 1) return;
    __threadfence();

    const int bb = t;                            // 128 threads == BB
    float anchor = 0.f, simp = 0.f, iimp = 0.f;
    #pragma unroll
    for (int m = 0; m < NMT; m++) {
        anchor += g_part[(0 * BB + bb) * NMT + m];
        simp   += g_part[(1 * BB + bb) * NMT + m];
        iimp   += g_part[(2 * BB + bb) * NMT + m];
    }
    const float nb = g_ntokf[bb];
    anchor /= nb;
    iimp   /= nb;
    simp   /= g_ntokf[Sidx[bb]];
    float per = fmaxf(1.f + iimp - anchor, 0.f) + fmaxf(1.f + simp - anchor, 0.f);

    #pragma unroll
    for (int o = 16; o > 0; o >>= 1) per += __shfl_down_sync(0xffffffffu, per, o);
    if (lane == 0) rsm[w] = per;
    __syncthreads();
    if (t == 0) {
        out[0] = (rsm[0] + rsm[1] + rsm[2] + rsm[3]) / (float)BB;
        g_ticket = 0u;                           // reset for next replay
        g_done   = 0u;
    }
}

// ---------------------------------------------------------------------------
extern "C" void kernel_launch(void* const* d_in, const int* in_sizes, int n_in,
                              void* d_out, int out_size) {
    const float* text  = (const float*)d_in[0];   // (B, N, D) f32
    const float* image = (const float*)d_in[1];   // (B, L, D) f32
    const float* tmask = (const float*)d_in[2];   // (B, N) f32
    const float* imask = (const float*)d_in[3];   // (B, L) f32
    const int*   Iidx  = (const int*)d_in[4];     // (B,) i32
    const int*   Sidx  = (const int*)d_in[5];     // (B,) i32
    (void)in_sizes; (void)n_in; (void)out_size;

    static int configured = 0;
    if (!configured) {
        cudaFuncSetAttribute(main_kernel,
                             cudaFuncAttributeMaxDynamicSharedMemorySize, SM_TOTAL);
        configured = 1;
    }

    convert_kernel<<<2048, 256>>>(text, image, tmask, imask);
    main_kernel<<<GRID, TPB, SM_TOTAL>>>(Iidx, Sidx, (float*)d_out);
}